// round 15
// baseline (speedup 1.0000x reference)
#include <cuda_runtime.h>
#include <cstdint>

// Problem constants
#define SEQ   32768
#define DMODEL 512
#define LROWS (SEQ * 8)          // 262144 head-rows
#define DH    64
#define NG    2048               // scan groups
#define TG    128                // rows per scan group (NG*TG == LROWS)

// ---------------- scratch (static device globals; allocation-free) ----------
__device__ float g_x [SEQ * DMODEL];   // x = inputs@W_in+b_in  (== [LROWS][64])
__device__ float g_fg[LROWS * DH];
__device__ float g_hr[LROWS * DH];
__device__ float g_og[LROWS * DH];
__device__ float g_gc[LROWS * DH];
__device__ float g_o [LROWS * DH];     // == [SEQ][512]
__device__ float g_Ab[NG * DH];
__device__ float g_Bb[NG * DH];
__device__ float g_Cb[NG * DH];

// ---------------- helpers ----------------------------------------------------
__device__ __forceinline__ unsigned f2tf(float f) {
    unsigned u;
    asm("cvt.rna.tf32.f32 %0, %1;" : "=r"(u) : "f"(f));
    return u;
}

__device__ __forceinline__ void mma_tf32(float (&d)[4], const unsigned (&a)[4],
                                         const unsigned (&b)[2]) {
    asm volatile(
        "mma.sync.aligned.m16n8k8.row.col.f32.tf32.tf32.f32 "
        "{%0,%1,%2,%3}, {%4,%5,%6,%7}, {%8,%9}, {%0,%1,%2,%3};"
        : "+f"(d[0]), "+f"(d[1]), "+f"(d[2]), "+f"(d[3])
        : "r"(a[0]), "r"(a[1]), "r"(a[2]), "r"(a[3]), "r"(b[0]), "r"(b[1]));
}

__device__ __forceinline__ float sigmoidf_(float x) {
    return 1.0f / (1.0f + __expf(-x));
}

// ================= K1/K7: C[M,512] = A[M,512] @ B[512,512] + bias ===========
// CTA tile 128x128, K-chunk 32, 256 threads (8 warps, 2m x 4n, warp 64x32).
__global__ __launch_bounds__(256, 2)
void gemm512_kernel(const float* __restrict__ A, const float* __restrict__ B,
                    const float* __restrict__ bias, float* __restrict__ C) {
    const int N = 512, K = 512;
    __shared__ unsigned As[128][34];
    __shared__ __align__(16) unsigned Bs[32][132];

    int tid  = threadIdx.x;
    int bm   = blockIdx.y * 128;
    int bn   = blockIdx.x * 128;
    int warp = tid >> 5, lane = tid & 31;
    int gl   = lane >> 2, tig = lane & 3;
    int wm   = (warp & 1) * 64;
    int wn   = (warp >> 1) * 32;

    float acc[4][4][4];
#pragma unroll
    for (int i = 0; i < 4; i++)
#pragma unroll
        for (int j = 0; j < 4; j++)
#pragma unroll
            for (int k = 0; k < 4; k++) acc[i][j][k] = 0.0f;

    for (int kc = 0; kc < K; kc += 32) {
        // load A tile 128x32
#pragma unroll
        for (int i = 0; i < 4; i++) {
            int l = tid + i * 256;
            int row = l >> 3, cv = l & 7;
            float4 v = *(const float4*)(A + (size_t)(bm + row) * K + kc + cv * 4);
            As[row][cv * 4 + 0] = f2tf(v.x);
            As[row][cv * 4 + 1] = f2tf(v.y);
            As[row][cv * 4 + 2] = f2tf(v.z);
            As[row][cv * 4 + 3] = f2tf(v.w);
        }
        // load B tile 32x128
#pragma unroll
        for (int i = 0; i < 4; i++) {
            int l = tid + i * 256;
            int row = l >> 5, cv = l & 31;
            float4 v = *(const float4*)(B + (size_t)(kc + row) * N + bn + cv * 4);
            uint4 u = make_uint4(f2tf(v.x), f2tf(v.y), f2tf(v.z), f2tf(v.w));
            *(uint4*)&Bs[row][cv * 4] = u;
        }
        __syncthreads();

#pragma unroll
        for (int ks = 0; ks < 32; ks += 8) {
            unsigned a[4][4], b[4][2];
#pragma unroll
            for (int mt = 0; mt < 4; mt++) {
                int r = wm + mt * 16 + gl;
                a[mt][0] = As[r][ks + tig];
                a[mt][1] = As[r + 8][ks + tig];
                a[mt][2] = As[r][ks + 4 + tig];
                a[mt][3] = As[r + 8][ks + 4 + tig];
            }
#pragma unroll
            for (int nt = 0; nt < 4; nt++) {
                int c = wn + nt * 8 + gl;
                b[nt][0] = Bs[ks + tig][c];
                b[nt][1] = Bs[ks + 4 + tig][c];
            }
#pragma unroll
            for (int mt = 0; mt < 4; mt++)
#pragma unroll
                for (int nt = 0; nt < 4; nt++) mma_tf32(acc[mt][nt], a[mt], b[nt]);
        }
        __syncthreads();
    }

#pragma unroll
    for (int mt = 0; mt < 4; mt++) {
        int r0 = bm + wm + mt * 16 + gl;
#pragma unroll
        for (int nt = 0; nt < 4; nt++) {
            int c0 = bn + wn + nt * 8 + tig * 2;
            float b0 = __ldg(bias + c0), b1 = __ldg(bias + c0 + 1);
            float2 v0 = make_float2(acc[mt][nt][0] + b0, acc[mt][nt][1] + b1);
            float2 v1 = make_float2(acc[mt][nt][2] + b0, acc[mt][nt][3] + b1);
            *(float2*)(C + (size_t)r0 * N + c0) = v0;
            *(float2*)(C + (size_t)(r0 + 8) * N + c0) = v1;
        }
    }
}

// ========== K2: fused gate GEMM + activations =================================
// Per CTA: 64 rows of x[LROWS][64]; GEMM vs [W_gates|W_og] (64x256) in one shot.
// Epilogue: fg=sig, hr=sig*tanh, og=sig written to global.
#define K2_APAD 66
#define K2_BPAD 260
#define K2_SMEM ((64 * K2_APAD + 64 * K2_BPAD) * 4)

__global__ __launch_bounds__(256, 2)
void fused_gates_kernel(const float* __restrict__ x,
                        const float* __restrict__ Wg, const float* __restrict__ bg,
                        const float* __restrict__ Wo, const float* __restrict__ bo,
                        float* __restrict__ fg, float* __restrict__ hr,
                        float* __restrict__ og) {
    extern __shared__ unsigned sm2[];
    unsigned (*As)[K2_APAD] = (unsigned(*)[K2_APAD])sm2;
    unsigned (*Bs)[K2_BPAD] = (unsigned(*)[K2_BPAD])(sm2 + 64 * K2_APAD);
    float    (*gs)[K2_BPAD] = (float(*)[K2_BPAD])(sm2 + 64 * K2_APAD); // reuse

    int tid = threadIdx.x;
    int rowbase = blockIdx.x * 64;

#pragma unroll
    for (int i = 0; i < 4; i++) {            // A: 64x64
        int l = tid + i * 256;
        int row = l >> 4, cv = l & 15;
        float4 v = *(const float4*)(x + (size_t)(rowbase + row) * 64 + cv * 4);
        As[row][cv * 4 + 0] = f2tf(v.x);
        As[row][cv * 4 + 1] = f2tf(v.y);
        As[row][cv * 4 + 2] = f2tf(v.z);
        As[row][cv * 4 + 3] = f2tf(v.w);
    }
    // B: 64x256 = [Wg | Wo]  -- 64*256 floats = 4096 float4 -> 16 iters of 256
#pragma unroll
    for (int i = 0; i < 16; i++) {
        int l = tid + i * 256;
        int row = l >> 6, cv = l & 63;
        const float* src = (cv < 48) ? (Wg + row * 192 + cv * 4)
                                     : (Wo + row * 64 + (cv - 48) * 4);
        float4 v = *(const float4*)src;
        Bs[row][cv * 4 + 0] = f2tf(v.x);
        Bs[row][cv * 4 + 1] = f2tf(v.y);
        Bs[row][cv * 4 + 2] = f2tf(v.z);
        Bs[row][cv * 4 + 3] = f2tf(v.w);
    }
    __syncthreads();

    int warp = tid >> 5, lane = tid & 31, gl = lane >> 2, tig = lane & 3;
    int wm = (warp >> 2) * 32;   // 2 m-warps of 32 rows
    int wn = (warp & 3) * 64;    // 4 n-warps of 64 cols
    float acc[2][8][4];
#pragma unroll
    for (int i = 0; i < 2; i++)
#pragma unroll
        for (int j = 0; j < 8; j++)
#pragma unroll
            for (int k = 0; k < 4; k++) acc[i][j][k] = 0.0f;

#pragma unroll
    for (int ks = 0; ks < 64; ks += 8) {
        unsigned a[2][4], b[8][2];
#pragma unroll
        for (int mt = 0; mt < 2; mt++) {
            int r = wm + mt * 16 + gl;
            a[mt][0] = As[r][ks + tig];
            a[mt][1] = As[r + 8][ks + tig];
            a[mt][2] = As[r][ks + 4 + tig];
            a[mt][3] = As[r + 8][ks + 4 + tig];
        }
#pragma unroll
        for (int nt = 0; nt < 8; nt++) {
            int c = wn + nt * 8 + gl;
            b[nt][0] = Bs[ks + tig][c];
            b[nt][1] = Bs[ks + 4 + tig][c];
        }
#pragma unroll
        for (int mt = 0; mt < 2; mt++)
#pragma unroll
            for (int nt = 0; nt < 8; nt++) mma_tf32(acc[mt][nt], a[mt], b[nt]);
    }
    __syncthreads();   // done reading Bs; now reuse as gs

#pragma unroll
    for (int mt = 0; mt < 2; mt++)
#pragma unroll
        for (int nt = 0; nt < 8; nt++) {
            int r = wm + mt * 16 + gl;
            int c = wn + nt * 8 + tig * 2;
            gs[r][c]     = acc[mt][nt][0];
            gs[r][c + 1] = acc[mt][nt][1];
            gs[r + 8][c]     = acc[mt][nt][2];
            gs[r + 8][c + 1] = acc[mt][nt][3];
        }
    __syncthreads();

    for (int idx = tid; idx < 64 * 64; idx += 256) {
        int row = idx >> 6, ch = idx & 63;
        float vfg = sigmoidf_(gs[row][ch] + __ldg(bg + ch));
        float vig = sigmoidf_(gs[row][64 + ch] + __ldg(bg + 64 + ch));
        float vh  = tanhf(gs[row][128 + ch] + __ldg(bg + 128 + ch));
        float vog = sigmoidf_(gs[row][192 + ch] + __ldg(bo + ch));
        size_t gi = (size_t)(rowbase + row) * 64 + ch;
        fg[gi] = vfg;
        hr[gi] = vig * vh;
        og[gi] = vog;
    }
}

// ================= scan pass 1: per-group (A,B) totals ========================
__global__ __launch_bounds__(256)
void scan_pass1(const float* __restrict__ fg, const float* __restrict__ hr,
                float* __restrict__ Ab, float* __restrict__ Bb) {
    int grp = blockIdx.x * 4 + (threadIdx.x >> 6);
    int ch  = threadIdx.x & 63;
    const float* pf = fg + (size_t)grp * TG * DH + ch;
    const float* pr = hr + (size_t)grp * TG * DH + ch;
    float a = 1.0f, b = 0.0f;
#pragma unroll 8
    for (int t = 0; t < TG; t++) {
        float f = pf[(size_t)t * DH];
        float r = pr[(size_t)t * DH];
        b = fmaf(b, f, r);
        a *= f;
    }
    Ab[grp * DH + ch] = a;
    Bb[grp * DH + ch] = b;
}

// ================= scan pass 2: serial carry scan over groups =================
__global__ void scan_pass2(const float* __restrict__ Ab, const float* __restrict__ Bb,
                           float* __restrict__ Cb) {
    int ch = threadIdx.x;   // 64 threads
    float v = 0.0f;
#pragma unroll 8
    for (int g = 0; g < NG; g++) {
        int i = g * DH + ch;
        float a = Ab[i], b = Bb[i];
        Cb[i] = v;               // carry INTO group g (exclusive)
        v = fmaf(v, a, b);
    }
}

// ================= scan pass 3: apply carries, produce gc = og * c ============
__global__ __launch_bounds__(256)
void scan_pass3(const float* __restrict__ fg, const float* __restrict__ hr,
                const float* __restrict__ og, const float* __restrict__ Cb,
                float* __restrict__ gc) {
    int grp = blockIdx.x * 4 + (threadIdx.x >> 6);
    int ch  = threadIdx.x & 63;
    size_t base = (size_t)grp * TG * DH + ch;
    float c = Cb[grp * DH + ch];
#pragma unroll 4
    for (int t = 0; t < TG; t++) {
        size_t i = base + (size_t)t * DH;
        float f = fg[i], r = hr[i];
        c = fmaf(f, c, r);
        gc[i] = og[i] * c;
    }
}

// ========== K6: o[LROWS,64] = gc @ W_c(64x64) + b_c ===========================
#define K6_APAD 66
#define K6_BPAD 68
#define K6_SMEM ((128 * K6_APAD + 64 * K6_BPAD) * 4)

__global__ __launch_bounds__(256, 2)
void out_proj_kernel(const float* __restrict__ gc, const float* __restrict__ Wc,
                     const float* __restrict__ bc, float* __restrict__ o) {
    extern __shared__ unsigned sm6[];
    unsigned (*As)[K6_APAD] = (unsigned(*)[K6_APAD])sm6;
    unsigned (*Bs)[K6_BPAD] = (unsigned(*)[K6_BPAD])(sm6 + 128 * K6_APAD);

    int tid = threadIdx.x;
    int rowbase = blockIdx.x * 128;

#pragma unroll
    for (int i = 0; i < 8; i++) {            // A: 128x64
        int l = tid + i * 256;
        int row = l >> 4, cv = l & 15;
        float4 v = *(const float4*)(gc + (size_t)(rowbase + row) * 64 + cv * 4);
        As[row][cv * 4 + 0] = f2tf(v.x);
        As[row][cv * 4 + 1] = f2tf(v.y);
        As[row][cv * 4 + 2] = f2tf(v.z);
        As[row][cv * 4 + 3] = f2tf(v.w);
    }
#pragma unroll
    for (int i = 0; i < 4; i++) {            // B: 64x64
        int l = tid + i * 256;
        int row = l >> 4, cv = l & 15;
        float4 v = *(const float4*)(Wc + (size_t)row * 64 + cv * 4);
        Bs[row][cv * 4 + 0] = f2tf(v.x);
        Bs[row][cv * 4 + 1] = f2tf(v.y);
        Bs[row][cv * 4 + 2] = f2tf(v.z);
        Bs[row][cv * 4 + 3] = f2tf(v.w);
    }
    __syncthreads();

    int warp = tid >> 5, lane = tid & 31, gl = lane >> 2, tig = lane & 3;
    int wm = (warp >> 1) * 32;   // 4 m-warps
    int wn = (warp & 1) * 32;    // 2 n-warps
    float acc[2][4][4];
#pragma unroll
    for (int i = 0; i < 2; i++)
#pragma unroll
        for (int j = 0; j < 4; j++)
#pragma unroll
            for (int k = 0; k < 4; k++) acc[i][j][k] = 0.0f;

#pragma unroll
    for (int ks = 0; ks < 64; ks += 8) {
        unsigned a[2][4], b[4][2];
#pragma unroll
        for (int mt = 0; mt < 2; mt++) {
            int r = wm + mt * 16 + gl;
            a[mt][0] = As[r][ks + tig];
            a[mt][1] = As[r + 8][ks + tig];
            a[mt][2] = As[r][ks + 4 + tig];
            a[mt][3] = As[r + 8][ks + 4 + tig];
        }
#pragma unroll
        for (int nt = 0; nt < 4; nt++) {
            int c = wn + nt * 8 + gl;
            b[nt][0] = Bs[ks + tig][c];
            b[nt][1] = Bs[ks + 4 + tig][c];
        }
#pragma unroll
        for (int mt = 0; mt < 2; mt++)
#pragma unroll
            for (int nt = 0; nt < 4; nt++) mma_tf32(acc[mt][nt], a[mt], b[nt]);
    }

#pragma unroll
    for (int mt = 0; mt < 2; mt++) {
        int r0 = rowbase + wm + mt * 16 + gl;
#pragma unroll
        for (int nt = 0; nt < 4; nt++) {
            int c0 = wn + nt * 8 + tig * 2;
            float b0 = __ldg(bc + c0), b1 = __ldg(bc + c0 + 1);
            float2 v0 = make_float2(acc[mt][nt][0] + b0, acc[mt][nt][1] + b1);
            float2 v1 = make_float2(acc[mt][nt][2] + b0, acc[mt][nt][3] + b1);
            *(float2*)(o + (size_t)r0 * 64 + c0) = v0;
            *(float2*)(o + (size_t)(r0 + 8) * 64 + c0) = v1;
        }
    }
}

// =============================== launcher =====================================
extern "C" void kernel_launch(void* const* d_in, const int* in_sizes, int n_in,
                              void* d_out, int out_size) {
    const float* inputs  = (const float*)d_in[0];
    const float* W_in    = (const float*)d_in[1];
    const float* b_in    = (const float*)d_in[2];
    const float* W_gates = (const float*)d_in[3];
    const float* b_gates = (const float*)d_in[4];
    const float* W_og    = (const float*)d_in[5];
    const float* b_og    = (const float*)d_in[6];
    const float* W_c     = (const float*)d_in[7];
    const float* b_c     = (const float*)d_in[8];
    const float* W_out   = (const float*)d_in[9];
    const float* b_out   = (const float*)d_in[10];
    float* out = (float*)d_out;

    void *px, *pfg, *phr, *pog, *pgc, *po, *pAb, *pBb, *pCb;
    cudaGetSymbolAddress(&px,  g_x);
    cudaGetSymbolAddress(&pfg, g_fg);
    cudaGetSymbolAddress(&phr, g_hr);
    cudaGetSymbolAddress(&pog, g_og);
    cudaGetSymbolAddress(&pgc, g_gc);
    cudaGetSymbolAddress(&po,  g_o);
    cudaGetSymbolAddress(&pAb, g_Ab);
    cudaGetSymbolAddress(&pBb, g_Bb);
    cudaGetSymbolAddress(&pCb, g_Cb);

    cudaFuncSetAttribute(fused_gates_kernel,
                         cudaFuncAttributeMaxDynamicSharedMemorySize, K2_SMEM);
    cudaFuncSetAttribute(out_proj_kernel,
                         cudaFuncAttributeMaxDynamicSharedMemorySize, K6_SMEM);

    dim3 gBig(DMODEL / 128, SEQ / 128);   // (4, 256)

    // K1: x = inputs @ W_in + b_in
    gemm512_kernel<<<gBig, 256>>>(inputs, W_in, b_in, (float*)px);

    // K2: gates + activations
    fused_gates_kernel<<<LROWS / 64, 256, K2_SMEM>>>(
        (const float*)px, W_gates, b_gates, W_og, b_og,
        (float*)pfg, (float*)phr, (float*)pog);

    // scan
    scan_pass1<<<NG / 4, 256>>>((const float*)pfg, (const float*)phr,
                                (float*)pAb, (float*)pBb);
    scan_pass2<<<1, 64>>>((const float*)pAb, (const float*)pBb, (float*)pCb);
    scan_pass3<<<NG / 4, 256>>>((const float*)pfg, (const float*)phr,
                                (const float*)pog, (const float*)pCb, (float*)pgc);

    // K6: o = gc @ W_c + b_c
    out_proj_kernel<<<LROWS / 128, 256, K6_SMEM>>>(
        (const float*)pgc, W_c, b_c, (float*)po);

    // K7: out = o @ W_out + b_out
    gemm512_kernel<<<gBig, 256>>>((const float*)po, W_out, b_out, out);
}